// round 17
// baseline (speedup 1.0000x reference)
#include <cuda_runtime.h>
#include <cuda_fp16.h>
#include <math.h>
#include <stdint.h>

#define BB 2
#define LL 2048
#define HH 16
#define DH 32
#define DM 512
#define SC2 0.063764568f             /* (1/sqrt(512)) * log2(e) */
#define QN (BB*LL*DM)                /* 2097152 */

__device__ float  g_q[BB*HH*LL*DH];
__device__ __half g_kh[BB*HH*LL*DH];
__device__ __half g_vh[BB*HH*LL*DH];   // transposed [b,h,dh,l]
__device__ __half g_ph[HH*LL*DH];
__device__ __half g_ctxh[BB*HH*LL*DH];
__device__ __half g_wh[5*DM*DM];       // fp16 Wq,Wk,Wv,Wp,Wo
__device__ __half g_inh[3*QN + LL*DM]; // fp16 query,key,value,pos

__device__ __forceinline__ void mma_f16(float& d0, float& d1, float& d2, float& d3,
                                        uint32_t a0, uint32_t a1, uint32_t a2, uint32_t a3,
                                        uint32_t b0, uint32_t b1) {
    asm volatile(
        "mma.sync.aligned.m16n8k16.row.col.f32.f16.f16.f32 "
        "{%0,%1,%2,%3}, {%4,%5,%6,%7}, {%8,%9}, {%0,%1,%2,%3};\n"
        : "+f"(d0), "+f"(d1), "+f"(d2), "+f"(d3)
        : "r"(a0), "r"(a1), "r"(a2), "r"(a3), "r"(b0), "r"(b1));
}

__device__ __forceinline__ void cp16(uint32_t dst, const void* src, int szbytes) {
    asm volatile("cp.async.cg.shared.global [%0], [%1], 16, %2;\n"
                 :: "r"(dst), "l"(src), "r"(szbytes));
}
__device__ __forceinline__ void cp_commit() {
    asm volatile("cp.async.commit_group;\n" ::: "memory");
}
template<int N>
__device__ __forceinline__ void cp_wait() {
    asm volatile("cp.async.wait_group %0;\n" :: "n"(N) : "memory");
}

// ---------------------------------------------------------------------------
// prep: weights + inputs -> fp16 in one launch.
// blocks [0,1280): weights (5 x 256 blocks); [1280, 4864): inputs.
// ---------------------------------------------------------------------------
__global__ __launch_bounds__(256)
void prep(const float* __restrict__ w0, const float* __restrict__ w1,
          const float* __restrict__ w2, const float* __restrict__ w3,
          const float* __restrict__ w4,
          const float* __restrict__ q, const float* __restrict__ k,
          const float* __restrict__ v, const float* __restrict__ p)
{
    int bx = blockIdx.x;
    if (bx < 1280) {
        const float* src[5] = {w0, w1, w2, w3, w4};
        int z = bx >> 8;
        int i = ((bx & 255) * 256 + threadIdx.x) * 4;
        float4 vv = *(const float4*)(src[z] + i);
        __half2 h0 = __floats2half2_rn(vv.x, vv.y);
        __half2 h1 = __floats2half2_rn(vv.z, vv.w);
        *(uint2*)(g_wh + (size_t)z * DM * DM + i) =
            make_uint2(*(uint32_t*)&h0, *(uint32_t*)&h1);
    } else {
        size_t i = ((size_t)(bx - 1280) * 256 + threadIdx.x) * 8;
        const float* src; size_t off;
        if (i < (size_t)QN)          { src = q; off = i; }
        else if (i < (size_t)2 * QN) { src = k; off = i - QN; }
        else if (i < (size_t)3 * QN) { src = v; off = i - 2 * (size_t)QN; }
        else                         { src = p; off = i - 3 * (size_t)QN; }
        float4 a = *(const float4*)(src + off);
        float4 b = *(const float4*)(src + off + 4);
        __half2 h0 = __floats2half2_rn(a.x, a.y);
        __half2 h1 = __floats2half2_rn(a.z, a.w);
        __half2 h2 = __floats2half2_rn(b.x, b.y);
        __half2 h3 = __floats2half2_rn(b.z, b.w);
        *(uint4*)(g_inh + i) = make_uint4(*(uint32_t*)&h0, *(uint32_t*)&h1,
                                          *(uint32_t*)&h2, *(uint32_t*)&h3);
    }
}

// ---------------------------------------------------------------------------
// fp16 GEMM core, cp.async double-buffered, m16n8k16, fp32 accum. (unchanged)
// ---------------------------------------------------------------------------
#define TGM 128
#define TGN 64
#define TGK 32
#define HGW 20
#define HA0 0
#define HA1 10240
#define HB0 20480
#define HB1 25600
#define GSMEM_BYTES 30720

__device__ __forceinline__ void gemm_core_h(
    const __half* __restrict__ A, const __half* __restrict__ W,
    const float* __restrict__ bias, void* __restrict__ Cv,
    int amode, int omode, char* smc)
{
    const int tid  = threadIdx.x;
    const int lane = tid & 31;
    const int warp = tid >> 5;
    const int g = lane >> 2;
    const int t = lane & 3;
    const int m0 = blockIdx.y * TGM;
    const int n0 = blockIdx.x * TGN;
    const uint32_t smb = (uint32_t)__cvta_generic_to_shared(smc);

    float acc[8][4];
#pragma unroll
    for (int nt = 0; nt < 8; nt++)
#pragma unroll
        for (int j = 0; j < 4; j++) acc[nt][j] = 0.f;

    auto issue = [&](int k0, int buf) {
        const int ab = buf ? HA1 : HA0;
        const int bb2 = buf ? HB1 : HB0;
#pragma unroll
        for (int i = 0; i < 2; i++) {
            int idx = tid + i * 256;
            int row = idx >> 2, c4 = idx & 3;
            int gm = m0 + row;
            const __half* src;
            if (amode == 0) {
                src = A + (size_t)gm * DM + k0 + c4 * 8;
            } else {
                int b = gm >> 11, l = gm & (LL - 1);
                int head = k0 >> 5;
                src = A + (((size_t)b * HH + head) * LL + l) * DH + c4 * 8;
            }
            cp16(smb + (uint32_t)(ab + row * 80 + c4 * 16), src, 16);
        }
        {
            int row = tid >> 2, c4 = tid & 3;
            const __half* src = W + (size_t)(n0 + row) * DM + k0 + c4 * 8;
            cp16(smb + (uint32_t)(bb2 + row * 80 + c4 * 16), src, 16);
        }
    };

    issue(0, 0);
    cp_commit();

    for (int c = 0; c < 16; c++) {
        cp_wait<0>();
        __syncthreads();
        if (c < 15) issue((c + 1) * TGK, (c + 1) & 1);
        cp_commit();

        const uint32_t* Aw = (const uint32_t*)(smc + ((c & 1) ? HA1 : HA0));
        const uint32_t* Bw = (const uint32_t*)(smc + ((c & 1) ? HB1 : HB0));
#pragma unroll
        for (int kt = 0; kt < 2; kt++) {
            int ar = warp * 16 + g;
            int aw0 = ar * HGW + t + 8 * kt;
            int aw1 = (ar + 8) * HGW + t + 8 * kt;
            uint32_t a0 = Aw[aw0], a1 = Aw[aw1];
            uint32_t a2 = Aw[aw0 + 4], a3 = Aw[aw1 + 4];
#pragma unroll
            for (int nt = 0; nt < 8; nt++) {
                int bw = (nt * 8 + g) * HGW + t + 8 * kt;
                mma_f16(acc[nt][0], acc[nt][1], acc[nt][2], acc[nt][3],
                        a0, a1, a2, a3, Bw[bw], Bw[bw + 4]);
            }
        }
    }

    const int sr = warp * 16 + g;
    const int gm = m0 + sr;
    const int bb = gm >> 11, l = gm & (LL - 1);
#pragma unroll
    for (int nt = 0; nt < 8; nt++) {
        int sc = nt * 8 + 2 * t;
        int n  = n0 + sc;
        float b0v = bias ? bias[n]     : 0.f;
        float b1v = bias ? bias[n + 1] : 0.f;
        float2 p0 = make_float2(acc[nt][0] + b0v, acc[nt][1] + b1v);
        float2 p1 = make_float2(acc[nt][2] + b0v, acc[nt][3] + b1v);
        if (omode == 0) {
            float* Cf = (float*)Cv;
            *(float2*)(Cf + (size_t)gm * DM + n)       = p0;
            *(float2*)(Cf + (size_t)(gm + 8) * DM + n) = p1;
        } else if (omode == 1) {
            float* Cf = (float*)Cv;
            int head = n >> 5, d = n & 31;
            float* base = Cf + (((size_t)bb * HH + head) * LL + l) * DH + d;
            *(float2*)(base)          = p0;
            *(float2*)(base + 8 * DH) = p1;
        } else if (omode == 2) {
            __half* Ch = (__half*)Cv;
            int head = n >> 5, d = n & 31;
            __half* base = Ch + (((size_t)bb * HH + head) * LL + l) * DH + d;
            __half2 h0 = __floats2half2_rn(p0.x, p0.y);
            __half2 h1 = __floats2half2_rn(p1.x, p1.y);
            *(__half2*)(base)          = h0;
            *(__half2*)(base + 8 * DH) = h1;
        } else {
            __half* Ch = (__half*)Cv;
            int head = n >> 5, d = n & 31;
            __half* base = Ch + (((size_t)bb * HH + head) * DH + d) * LL + l;
            base[0]      = __float2half_rn(p0.x);
            base[LL]     = __float2half_rn(p0.y);
            base[8]      = __float2half_rn(p1.x);
            base[LL + 8] = __float2half_rn(p1.y);
        }
    }
}

__global__ __launch_bounds__(256)
void qkvp_gemm(const float* __restrict__ bq, const float* __restrict__ bk,
               const float* __restrict__ bv)
{
    extern __shared__ char smc[];
    int z = blockIdx.z;
    if (z == 3 && blockIdx.y >= LL / TGM) return;
    const __half* A = g_inh + (size_t)z * QN;
    const __half* W = g_wh + (size_t)z * DM * DM;
    const float* b = (z == 0) ? bq : (z == 1) ? bk : (z == 2) ? bv : nullptr;
    void* C; int omode;
    if (z == 0)      { C = g_q;  omode = 1; }
    else if (z == 1) { C = g_kh; omode = 2; }
    else if (z == 2) { C = g_vh; omode = 3; }
    else             { C = g_ph; omode = 2; }
    gemm_core_h(A, W, b, C, 0, omode, smc);
}

__global__ __launch_bounds__(256)
void wo_gemm(const float* __restrict__ bias, float* __restrict__ C)
{
    extern __shared__ char smc[];
    gemm_core_h(g_ctxh, g_wh + (size_t)4 * DM * DM, bias, C, 1, 0, smc);
}

// ---------------------------------------------------------------------------
// FA2-style uniform-warp attention with MIRRORED resolved fp16 ring.
// Ring rows are 192 halfs wide (stride 198): cells [128,191) mirror [0,63).
// Writers mirror stores when wc<64 (uniform per tile); readers index rb+c
// directly with NO per-element modulo (rb in [0,127], c<=63 -> idx<=190).
// Shift: r=j-i; r<=0 -> p[L-1+r]; r==1 -> 0; r>=2 -> row i+1 uses p[r-2]
// (resolved ring: W[s][r] stored at row s-(r>=1); mixed tile iff r0==0)
// ---------------------------------------------------------------------------
#define TI 64
#define TJ 64
#define HW 20     /* K/P/Q tile word stride (80B rows) */
#define VW 36     /* V^T word stride (144B rows) */
#define WSTRH 198 /* ring half stride: 99 words == 3 mod 32 */
#define RING 128

#define QU_B 0        /* 64x80  = 5120 (reused: K buf1 after frag hoist) */
#define QV_B 5120     /* 65x80  = 5200 (bytes<4608 reused: V buf1; qv64 safe) */
#define K0_B 10320
#define V0_B 15440    /* 32x144 = 4608 */
#define P0_B 20048
#define P1_B 25168
#define SW_B 30288    /* 64x198x2 = 25344 */
#define SMEM_BYTES 55632

__global__ __launch_bounds__(128, 4)
void attn_mma(const float* __restrict__ qd, const __half* __restrict__ kd,
              const __half* __restrict__ vd, const __half* __restrict__ pd,
              const float* __restrict__ ub, const float* __restrict__ vb,
              __half* __restrict__ ctx)
{
    extern __shared__ char smc[];
    __half* sWh = (__half*)(smc + SW_B);
    const uint32_t smb = (uint32_t)__cvta_generic_to_shared(smc);

    const int tid  = threadIdx.x;
    const int lane = tid & 31;
    const int warp = tid >> 5;
    const int g = lane >> 2, tq = lane & 3;
    const int I0 = blockIdx.x * TI;
    const int h = blockIdx.y, b = blockIdx.z;

    const float*  qbase  = qd + (size_t)(b * HH + h) * LL * DH;
    const __half* kbase  = kd + (size_t)(b * HH + h) * LL * DH;
    const __half* vtbase = vd + (size_t)(b * HH + h) * DH * LL;
    const __half* pbase  = pd + (size_t)h * LL * DH;

    const int KbufB[2] = {K0_B, QU_B};
    const int VbufB[2] = {V0_B, QV_B};
    const int PbufB[2] = {P0_B, P1_B};

    // ---- stage Qu (64 rows) / Qv (65 rows), rn-fp16, pre-scaled by SC2
    for (int idx = tid; idx < TI * 8; idx += 128) {
        int row = idx >> 3, c4 = idx & 7;
        float4 q  = *(const float4*)(qbase + (size_t)(I0 + row) * DH + c4 * 4);
        float4 u4 = *(const float4*)(ub + h * DH + c4 * 4);
        __half2 h0 = __floats2half2_rn((q.x + u4.x) * SC2, (q.y + u4.y) * SC2);
        __half2 h1 = __floats2half2_rn((q.z + u4.z) * SC2, (q.w + u4.w) * SC2);
        *(uint2*)(smc + QU_B + row * 80 + c4 * 8) =
            make_uint2(*(uint32_t*)&h0, *(uint32_t*)&h1);
    }
    for (int idx = tid; idx < (TI + 1) * 8; idx += 128) {
        int row = idx >> 3, c4 = idx & 7;
        int gr = I0 + row;
        uint2 o = make_uint2(0u, 0u);
        if (gr < LL) {
            float4 q  = *(const float4*)(qbase + (size_t)gr * DH + c4 * 4);
            float4 v4 = *(const float4*)(vb + h * DH + c4 * 4);
            __half2 h0 = __floats2half2_rn((q.x + v4.x) * SC2, (q.y + v4.y) * SC2);
            __half2 h1 = __floats2half2_rn((q.z + v4.z) * SC2, (q.w + v4.w) * SC2);
            o = make_uint2(*(uint32_t*)&h0, *(uint32_t*)&h1);
        }
        *(uint2*)(smc + QV_B + row * 80 + c4 * 8) = o;
    }
    // ---- stage prologue band cols r in [-I0-64, -I0-1] into P1
    for (int idx = tid; idx < 64 * 4; idx += 128) {
        int row = idx >> 2, c4 = idx & 3;
        int r = -I0 - 64 + row;
        uint4 v = make_uint4(0u, 0u, 0u, 0u);
        if (r <= 0) { if (r >= 1 - LL) v = *(const uint4*)(pbase + (size_t)(LL - 1 + r) * DH + c4 * 8); }
        else if (r >= 2 && r <= LL + 1) v = *(const uint4*)(pbase + (size_t)(r - 2) * DH + c4 * 8);
        *(uint4*)(smc + P1_B + row * 80 + c4 * 16) = v;
    }
    __syncthreads();

    auto issueKPV = [&](int Jk, int Jp, int nb) {
#pragma unroll
        for (int i = 0; i < 2; i++) {
            int idx = tid + i * 128;
            int row = idx >> 2, c4 = idx & 3;
            cp16(smb + (uint32_t)(KbufB[nb] + row * 80 + c4 * 16),
                 kbase + (size_t)(Jk + row) * DH + c4 * 8, 16);
            int r = Jp - I0 + row;
            const __half* psrc = pbase;
            int sz = 0;
            if (r <= 0) { if (r >= 1 - LL) { psrc = pbase + (size_t)(LL - 1 + r) * DH + c4 * 8; sz = 16; } }
            else if (r >= 2 && r <= LL + 1) { psrc = pbase + (size_t)(r - 2) * DH + c4 * 8; sz = 16; }
            cp16(smb + (uint32_t)(PbufB[nb] + row * 80 + c4 * 16), psrc, sz);
        }
#pragma unroll
        for (int i = 0; i < 2; i++) {
            int idx = tid + i * 128;
            int ch = idx >> 3, c8 = idx & 7;
            cp16(smb + (uint32_t)(VbufB[nb] + ch * 144 + c8 * 16),
                 vtbase + (size_t)ch * LL + Jk + c8 * 8, 16);
        }
    };

    issueKPV(0, 0, 0);
    cp_commit();

    // ---- hoist A-frags (rows 16w..16w+15)
    const uint32_t* QuW = (const uint32_t*)(smc + QU_B);
    const uint32_t* QvW = (const uint32_t*)(smc + QV_B);
    uint32_t afu[2][4], afv[2][4];
#pragma unroll
    for (int kt = 0; kt < 2; kt++) {
        int w0 = (16 * warp + g) * HW + tq + 8 * kt;
        int w1 = w0 + 8 * HW;
        afu[kt][0] = QuW[w0];     afu[kt][1] = QuW[w1];
        afu[kt][2] = QuW[w0 + 4]; afu[kt][3] = QuW[w1 + 4];
        afv[kt][0] = QvW[w0];     afv[kt][1] = QvW[w1];
        afv[kt][2] = QvW[w0 + 4]; afv[kt][3] = QvW[w1 + 4];
    }

    // ---- prologue W from P1 (all r<=0: resolved row == source row)
    {
        const int slotbase = ((-I0 - 64) + 4096) & (RING - 1);
        const uint32_t* Pw = (const uint32_t*)(smc + P1_B);
#pragma unroll
        for (int nt = 0; nt < 8; nt++) {
            float d0 = 0.f, d1 = 0.f, d2 = 0.f, d3 = 0.f;
#pragma unroll
            for (int kt = 0; kt < 2; kt++) {
                int bw = (nt * 8 + g) * HW + tq + 8 * kt;
                mma_f16(d0, d1, d2, d3,
                        afv[kt][0], afv[kt][1], afv[kt][2], afv[kt][3],
                        Pw[bw], Pw[bw + 4]);
            }
            int wr = 16 * warp + g;
            int wc = slotbase + nt * 8 + 2 * tq;
            __half2 lo = __floats2half2_rn(d0, d1);
            __half2 hi = __floats2half2_rn(d2, d3);
            *(__half2*)&sWh[wr * WSTRH + wc]       = lo;
            *(__half2*)&sWh[(wr + 8) * WSTRH + wc] = hi;
            if (wc < 64) {
                *(__half2*)&sWh[wr * WSTRH + wc + 128]       = lo;
                *(__half2*)&sWh[(wr + 8) * WSTRH + wc + 128] = hi;
            }
        }
    }
    __syncthreads();   // ring ready; QU/QV/P1 free for reuse

    // ---- persistent state
    float dacc[4][4];
#pragma unroll
    for (int nt = 0; nt < 4; nt++)
#pragma unroll
        for (int j = 0; j < 4; j++) dacc[nt][j] = 0.f;
    float rmax0 = -INFINITY, rmax1 = -INFINITY, rsum0 = 0.f, rsum1 = 0.f;

    const int row0 = 16 * warp + g;
    const __half* w0row = sWh + row0 * WSTRH;
    const __half* w1row = w0row + 8 * WSTRH;

    for (int t = 0; t < 32; t++) {
        const int J0 = t * TJ;
        cp_wait<0>();
        __syncthreads();   // tile t visible; prev tile fully consumed

        if (t < 31) {
            const int Jn = J0 + TJ;
            const int Jc = (Jn < LL) ? Jn : (LL - TJ);
            issueKPV(Jc, Jn, (t + 1) & 1);
            cp_commit();
        }

        const uint32_t* Kw = (const uint32_t*)(smc + KbufB[t & 1]);
        const uint32_t* Pw = (const uint32_t*)(smc + PbufB[t & 1]);
        const uint32_t* Vw = (const uint32_t*)(smc + VbufB[t & 1]);
        const int r0 = J0 - I0;
        const int slotbase = (r0 + 4096) & (RING - 1);

        // ---- W band MMA + resolved store (mirrored)
        {
            float wacc[8][4];
#pragma unroll
            for (int nt = 0; nt < 8; nt++) {
                float d0 = 0.f, d1 = 0.f, d2 = 0.f, d3 = 0.f;
#pragma unroll
                for (int kt = 0; kt < 2; kt++) {
                    int bw = (nt * 8 + g) * HW + tq + 8 * kt;
                    mma_f16(d0, d1, d2, d3,
                            afv[kt][0], afv[kt][1], afv[kt][2], afv[kt][3],
                            Pw[bw], Pw[bw + 4]);
                }
                wacc[nt][0] = d0; wacc[nt][1] = d1; wacc[nt][2] = d2; wacc[nt][3] = d3;
            }
            if (r0 != 0) {
                const int sh = (r0 >= 1) ? 1 : 0;
                const int wr = row0 - sh;
#pragma unroll
                for (int nt = 0; nt < 8; nt++) {
                    int wc = slotbase + nt * 8 + 2 * tq;
                    __half2 lo = __floats2half2_rn(wacc[nt][0], wacc[nt][1]);
                    __half2 hi = __floats2half2_rn(wacc[nt][2], wacc[nt][3]);
                    if (wr >= 0) {
                        *(__half2*)&sWh[wr * WSTRH + wc] = lo;
                        if (wc < 64) *(__half2*)&sWh[wr * WSTRH + wc + 128] = lo;
                    }
                    *(__half2*)&sWh[(wr + 8) * WSTRH + wc] = hi;
                    if (wc < 64) *(__half2*)&sWh[(wr + 8) * WSTRH + wc + 128] = hi;
                }
            } else {
                // mixed tile (r0==0, once per block): per-element resolve; wc<64 always
#pragma unroll
                for (int nt = 0; nt < 8; nt++) {
                    int c0 = nt * 8 + 2 * tq;
#pragma unroll
                    for (int e = 0; e < 2; e++) {
                        int c = c0 + e;
                        int sh = (c >= 1) ? 1 : 0;
                        int w0r = row0 - sh;
                        __half v0 = __float2half_rn(wacc[nt][e]);
                        __half v1 = __float2half_rn(wacc[nt][2 + e]);
                        if (w0r >= 0) {
                            sWh[w0r * WSTRH + c]       = v0;
                            sWh[w0r * WSTRH + c + 128] = v0;
                        }
                        sWh[(row0 + 8 - sh) * WSTRH + c]       = v1;
                        sWh[(row0 + 8 - sh) * WSTRH + c + 128] = v1;
                    }
                }
            }
            // extra row 64 -> resolved row 63 (only where its r >= 1)
            if (tid < 64) {
                int r = r0 + tid;
                if (r >= 1) {
                    const __half2* qv64 = (const __half2*)(smc + QV_B + 64 * 80);
                    const __half2* pr   = (const __half2*)(smc + PbufB[t & 1] + tid * 80);
                    float s = 0.f;
#pragma unroll
                    for (int c = 0; c < 16; c++) {
                        float2 a = __half22float2(qv64[c]);
                        float2 bb2 = __half22float2(pr[c]);
                        s += a.x * bb2.x + a.y * bb2.y;
                    }
                    int wc = slotbase + tid;
                    __half hv = __float2half_rn(s);
                    sWh[63 * WSTRH + wc] = hv;
                    if (wc < 64) sWh[63 * WSTRH + wc + 128] = hv;
                }
            }
        }

        // ---- S MMA (register accumulator)
        float sacc[8][4];
#pragma unroll
        for (int nt = 0; nt < 8; nt++) {
            float d0 = 0.f, d1 = 0.f, d2 = 0.f, d3 = 0.f;
#pragma unroll
            for (int kt = 0; kt < 2; kt++) {
                int bw = (nt * 8 + g) * HW + tq + 8 * kt;
                mma_f16(d0, d1, d2, d3,
                        afu[kt][0], afu[kt][1], afu[kt][2], afu[kt][3],
                        Kw[bw], Kw[bw + 4]);
            }
            sacc[nt][0] = d0; sacc[nt][1] = d1; sacc[nt][2] = d2; sacc[nt][3] = d3;
        }

        __syncthreads();   // ring W(t) complete

        // ---- in-fragment gather + softmax (log2 domain); no per-element mod
        const int rb0 = (J0 - I0 - row0 + 8192) & (RING - 1);
        const int rb1 = (J0 - I0 - row0 - 8 + 8192) & (RING - 1);
        const __half* g0 = w0row + rb0;
        const __half* g1 = w1row + rb1;
        float m0 = -INFINITY, m1 = -INFINITY;
#pragma unroll
        for (int nt = 0; nt < 8; nt++) {
            int c = nt * 8 + 2 * tq;
            sacc[nt][0] += __half2float(g0[c]);
            sacc[nt][1] += __half2float(g0[c + 1]);
            sacc[nt][2] += __half2float(g1[c]);
            sacc[nt][3] += __half2float(g1[c + 1]);
            m0 = fmaxf(m0, fmaxf(sacc[nt][0], sacc[nt][1]));
            m1 = fmaxf(m1, fmaxf(sacc[nt][2], sacc[nt][3]));
        }
        m0 = fmaxf(m0, __shfl_xor_sync(0xffffffffu, m0, 1));
        m0 = fmaxf(m0, __shfl_xor_sync(0xffffffffu, m0, 2));
        m1 = fmaxf(m1, __shfl_xor_sync(0xffffffffu, m1, 1));
        m1 = fmaxf(m1, __shfl_xor_sync(0xffffffffu, m1, 2));
        float mnew0 = fmaxf(rmax0, m0);
        float mnew1 = fmaxf(rmax1, m1);
        float corr0 = exp2f(rmax0 - mnew0);   // first tile: 2^-inf = 0
        float corr1 = exp2f(rmax1 - mnew1);

        uint32_t ha[8], hb[8];
        float csum0 = 0.f, csum1 = 0.f;
#pragma unroll
        for (int nt = 0; nt < 8; nt++) {
            __half2 h0 = __floats2half2_rn(exp2f(sacc[nt][0] - mnew0),
                                           exp2f(sacc[nt][1] - mnew0));
            __half2 h1 = __floats2half2_rn(exp2f(sacc[nt][2] - mnew1),
                                           exp2f(sacc[nt][3] - mnew1));
            float2 f0 = __half22float2(h0);
            float2 f1 = __half22float2(h1);
            csum0 += f0.x + f0.y;
            csum1 += f1.x + f1.y;
            ha[nt] = *(uint32_t*)&h0;
            hb[nt] = *(uint32_t*)&h1;
        }
        csum0 += __shfl_xor_sync(0xffffffffu, csum0, 1);
        csum0 += __shfl_xor_sync(0xffffffffu, csum0, 2);
        csum1 += __shfl_xor_sync(0xffffffffu, csum1, 1);
        csum1 += __shfl_xor_sync(0xffffffffu, csum1, 2);
        rsum0 = rsum0 * corr0 + csum0;
        rsum1 = rsum1 * corr1 + csum1;
        rmax0 = mnew0; rmax1 = mnew1;

        // ---- rescale + PV MMA (P from registers)
#pragma unroll
        for (int nt = 0; nt < 4; nt++) {
            dacc[nt][0] *= corr0; dacc[nt][1] *= corr0;
            dacc[nt][2] *= corr1; dacc[nt][3] *= corr1;
        }
#pragma unroll
        for (int kt = 0; kt < 4; kt++) {
            uint32_t a0 = ha[2 * kt], a1 = hb[2 * kt];
            uint32_t a2 = ha[2 * kt + 1], a3 = hb[2 * kt + 1];
#pragma unroll
            for (int nt = 0; nt < 4; nt++) {
                int bw = (nt * 8 + g) * VW + tq + 8 * kt;
                mma_f16(dacc[nt][0], dacc[nt][1], dacc[nt][2], dacc[nt][3],
                        a0, a1, a2, a3, Vw[bw], Vw[bw + 4]);
            }
        }
    }

    // ---- finalize: per-lane normalize, ctx as fp16
    {
        float inv0 = 1.f / rsum0;
        float inv1 = 1.f / rsum1;
        __half* ob = ctx + (size_t)(b * HH + h) * LL * DH;
#pragma unroll
        for (int nt = 0; nt < 4; nt++) {
            int sc = nt * 8 + 2 * tq;
            __half2 h0 = __floats2half2_rn(dacc[nt][0] * inv0, dacc[nt][1] * inv0);
            __half2 h1 = __floats2half2_rn(dacc[nt][2] * inv1, dacc[nt][3] * inv1);
            *(__half2*)(ob + (size_t)(I0 + row0) * DH + sc)     = h0;
            *(__half2*)(ob + (size_t)(I0 + row0 + 8) * DH + sc) = h1;
        }
    }
}

// ---------------------------------------------------------------------------
extern "C" void kernel_launch(void* const* d_in, const int* in_sizes, int n_in,
                              void* d_out, int out_size)
{
    const float* query = (const float*)d_in[0];
    const float* key   = (const float*)d_in[1];
    const float* value = (const float*)d_in[2];
    const float* pos   = (const float*)d_in[3];
    const float* Wq    = (const float*)d_in[4];
    const float* bq    = (const float*)d_in[5];
    const float* Wk    = (const float*)d_in[6];
    const float* bk    = (const float*)d_in[7];
    const float* Wv    = (const float*)d_in[8];
    const float* bv    = (const float*)d_in[9];
    const float* Wp    = (const float*)d_in[10];
    const float* ub    = (const float*)d_in[11];
    const float* vb    = (const float*)d_in[12];
    const float* Wo    = (const float*)d_in[13];
    const float* bo    = (const float*)d_in[14];

    float *pq;
    __half *pk, *pv, *pp, *pctx;
    cudaGetSymbolAddress((void**)&pq,   g_q);
    cudaGetSymbolAddress((void**)&pk,   g_kh);
    cudaGetSymbolAddress((void**)&pv,   g_vh);
    cudaGetSymbolAddress((void**)&pp,   g_ph);
    cudaGetSymbolAddress((void**)&pctx, g_ctxh);

    static int attr_set = 0;
    if (!attr_set) {
        cudaFuncSetAttribute(attn_mma, cudaFuncAttributeMaxDynamicSharedMemorySize, SMEM_BYTES);
        cudaFuncSetAttribute(qkvp_gemm, cudaFuncAttributeMaxDynamicSharedMemorySize, GSMEM_BYTES);
        cudaFuncSetAttribute(wo_gemm, cudaFuncAttributeMaxDynamicSharedMemorySize, GSMEM_BYTES);
        attr_set = 1;
    }

    // weights + inputs -> fp16, one launch
    prep<<<1280 + (3 * QN + LL * DM) / 2048, 256>>>(
        Wq, Wk, Wv, Wp, Wo, query, key, value, pos);

    qkvp_gemm<<<dim3(DM / TGN, (BB * LL) / TGM, 4), 256, GSMEM_BYTES>>>(bq, bk, bv);

    attn_mma<<<dim3(LL / TI, HH, BB), 128, SMEM_BYTES>>>(pq, pk, pv, pp, ub, vb, pctx);

    wo_gemm<<<dim3(DM / TGN, (BB * LL) / TGM), 256, GSMEM_BYTES>>>(
        bo, (float*)d_out);
}